// round 9
// baseline (speedup 1.0000x reference)
#include <cuda_runtime.h>

#define N_VERTICES 1000000
#define N_EDGES    16000000

// Scratch accumulator. Zero-initialized at module load; finalize_r resets it
// after consuming it, so every graph replay starts clean.
__device__ float g_cbar[N_VERTICES];

// Fork-join resources, created once at static-init time (before the harness
// takes its memory checkpoints). No device-memory allocation APIs involved.
static cudaStream_t g_s2;
static cudaEvent_t  g_ev_fork, g_ev_join;
static struct StreamInit {
    StreamInit() {
        cudaStreamCreateWithFlags(&g_s2, cudaStreamNonBlocking);
        cudaEventCreateWithFlags(&g_ev_fork, cudaEventDisableTiming);
        cudaEventCreateWithFlags(&g_ev_join, cudaEventDisableTiming);
    }
} g_stream_init;

// Scatter: 8 edges per thread (2x int4 index loads + 4x float4 edge_attr
// loads + 8 spread-address fp32 REDs). Sits at the REDG issue/L2-atomic
// floor; keep minimal. 128 threads x 15625 blocks = exactly 2M threads.
__global__ void __launch_bounds__(128, 16)
scatter_kernel(const int* __restrict__ src_idx,
               const float* __restrict__ edge_attr) {
    unsigned t = blockIdx.x * blockDim.x + threadIdx.x;   // [0, 2,000,000)
    const int4*   idx4 = (const int4*)src_idx;
    const float4* ea4  = (const float4*)edge_attr;

    int4   ia = idx4[2u * t];
    int4   ib = idx4[2u * t + 1u];
    float4 e0 = ea4[4u * t];
    float4 e1 = ea4[4u * t + 1u];
    float4 e2 = ea4[4u * t + 2u];
    float4 e3 = ea4[4u * t + 3u];

    atomicAdd(&g_cbar[ia.x], e0.y);
    atomicAdd(&g_cbar[ia.y], e0.w);
    atomicAdd(&g_cbar[ia.z], e1.y);
    atomicAdd(&g_cbar[ia.w], e1.w);
    atomicAdd(&g_cbar[ib.x], e2.y);
    atomicAdd(&g_cbar[ib.y], e2.w);
    atomicAdd(&g_cbar[ib.z], e3.y);
    atomicAdd(&g_cbar[ib.w], e3.w);
}

// Concurrent copy (runs on the forked stream, overlapped with scatter):
// writes full (b, x, placeholder) rows as 3x float4 per 4 vertices so every
// out sector is fully populated; finalize_r later overwrites the r bytes
// (disjoint-byte WAW, ordered by the join event).
__global__ void __launch_bounds__(256, 8)
copy_bx_kernel(const float* __restrict__ vertex_attr,
               float* __restrict__ out) {
    unsigned q = blockIdx.x * blockDim.x + threadIdx.x;   // [0, 250K)
    if (q < N_VERTICES / 4) {
        const float4* va4 = (const float4*)vertex_attr;
        float4 v01 = va4[2u * q];        // (b0,x0,b1,x1)
        float4 v23 = va4[2u * q + 1u];   // (b2,x2,b3,x3)
        float4* o4 = (float4*)(out + 12u * (unsigned long long)q);
        o4[0] = make_float4(v01.x, v01.y, v01.x, v01.z);  // b0,x0,(r0),b1
        o4[1] = make_float4(v01.w, v01.z, v23.x, v23.y);  // x1,(r1),b2,x2
        o4[2] = make_float4(v23.x, v23.z, v23.w, v23.z);  // (r2),b3,x3,(r3)
    }
}

// Finalize: r column only + accumulator reset. All traffic is L2-hot
// (cbar from the atomics, vertex_attr from copy_bx, out sectors from copy_bx).
__global__ void __launch_bounds__(256, 8)
finalize_r_kernel(const float* __restrict__ vertex_attr,
                  float* __restrict__ out) {
    unsigned q = blockIdx.x * blockDim.x + threadIdx.x;   // [0, 250K)
    if (q < N_VERTICES / 4) {
        const float4* va4 = (const float4*)vertex_attr;
        float4 v01 = va4[2u * q];        // (b0,x0,b1,x1)
        float4 v23 = va4[2u * q + 1u];   // (b2,x2,b3,x3)

        float4* cp = (float4*)&g_cbar[4u * q];
        float4 c = *cp;
        *cp = make_float4(0.0f, 0.0f, 0.0f, 0.0f);

        float* o = out + 12u * (unsigned long long)q;
        o[2]  = v01.x - c.x;   // r0
        o[5]  = v01.z - c.y;   // r1
        o[8]  = v23.x - c.z;   // r2
        o[11] = v23.z - c.w;   // r3
    }
}

extern "C" void kernel_launch(void* const* d_in, const int* in_sizes, int n_in,
                              void* d_out, int out_size) {
    // Inputs (JAX x64 disabled => "int64" arrays are int32 on device):
    // 0: vertex_attr (1M x 2) f32, 1: edgeij_pair (2 x 16M) i32 (row0 = src),
    // 2: edge_attr (16M x 2) f32, 3: g (unused), 4: batch (unused)
    const float* vertex_attr = (const float*)d_in[0];
    const int*   edge_src    = (const int*)d_in[1];
    const float* edge_attr   = (const float*)d_in[2];
    float*       out         = (float*)d_out;

    // Fork: copy_bx runs concurrently with scatter on g_s2.
    cudaEventRecord(g_ev_fork, 0);
    cudaStreamWaitEvent(g_s2, g_ev_fork, 0);
    {
        const int threads = 256;
        const int blocks  = (N_VERTICES / 4 + threads - 1) / threads;  // 977
        copy_bx_kernel<<<blocks, threads, 0, g_s2>>>(vertex_attr, out);
    }
    cudaEventRecord(g_ev_join, g_s2);

    // Scatter on the main stream: 16M edges / 8 = 2M threads = 128 x 15625.
    {
        const int threads = 128;
        const int blocks  = (N_EDGES / 8) / threads;  // 15625, exact
        scatter_kernel<<<blocks, threads>>>(edge_src, edge_attr);
    }

    // Join, then finalize the r column + reset accumulator.
    cudaStreamWaitEvent(0, g_ev_join, 0);
    {
        const int threads = 256;
        const int blocks  = (N_VERTICES / 4 + threads - 1) / threads;  // 977
        finalize_r_kernel<<<blocks, threads>>>(vertex_attr, out);
    }
}

// round 10
// speedup vs baseline: 1.0018x; 1.0018x over previous
#include <cuda_runtime.h>

#define N_VERTICES 1000000
#define N_EDGES    16000000

// Scratch accumulator. Zero-initialized at module load; finalize_kernel
// resets it after consuming it, so every graph replay starts clean.
__device__ float g_cbar[N_VERTICES];

// Scatter: 8 edges per thread (2x int4 index loads + 4x float4 edge_attr
// loads + 8 spread-address fp32 REDs). Sits at the SM-LSU per-lane RED floor
// (~330 cyc/warp); keep minimal. 128 threads x 15625 blocks = exactly 2M
// threads. Fires the PDL trigger at block start so the finalize kernel can
// begin its scatter-independent prefix during our last wave.
__global__ void __launch_bounds__(128, 16)
scatter_kernel(const int* __restrict__ src_idx,
               const float* __restrict__ edge_attr) {
    cudaTriggerProgrammaticLaunchCompletion();

    unsigned t = blockIdx.x * blockDim.x + threadIdx.x;   // [0, 2,000,000)
    const int4*   idx4 = (const int4*)src_idx;
    const float4* ea4  = (const float4*)edge_attr;

    int4   ia = idx4[2u * t];
    int4   ib = idx4[2u * t + 1u];
    float4 e0 = ea4[4u * t];
    float4 e1 = ea4[4u * t + 1u];
    float4 e2 = ea4[4u * t + 2u];
    float4 e3 = ea4[4u * t + 3u];

    atomicAdd(&g_cbar[ia.x], e0.y);
    atomicAdd(&g_cbar[ia.y], e0.w);
    atomicAdd(&g_cbar[ia.z], e1.y);
    atomicAdd(&g_cbar[ia.w], e1.w);
    atomicAdd(&g_cbar[ib.x], e2.y);
    atomicAdd(&g_cbar[ib.y], e2.w);
    atomicAdd(&g_cbar[ib.z], e3.y);
    atomicAdd(&g_cbar[ib.w], e3.w);
}

// Finalize, PDL-launched: the pre-sync prefix (vertex loads + full-row stores
// with placeholder r) overlaps scatter's tail; after
// cudaGridDependencySynchronize() only ~12MB of L2-hot traffic remains
// (cbar read+reset, 4 scalar r overwrites into just-written sectors).
__global__ void __launch_bounds__(256, 8)
finalize_kernel(const float* __restrict__ vertex_attr,
                float* __restrict__ out) {
    unsigned q = blockIdx.x * blockDim.x + threadIdx.x;   // [0, 250K)
    if (q < N_VERTICES / 4) {
        const float4* va4 = (const float4*)vertex_attr;
        float4 v01 = va4[2u * q];        // (b0,x0,b1,x1)
        float4 v23 = va4[2u * q + 1u];   // (b2,x2,b3,x3)

        // Scatter-independent: populate full rows (r slots get placeholders).
        float4* o4 = (float4*)(out + 12u * (unsigned long long)q);
        o4[0] = make_float4(v01.x, v01.y, v01.x, v01.z);  // b0,x0,(r0),b1
        o4[1] = make_float4(v01.w, v01.z, v23.x, v23.y);  // x1,(r1),b2,x2
        o4[2] = make_float4(v23.x, v23.z, v23.w, v23.z);  // (r2),b3,x3,(r3)

        // Wait for all scatter REDs to be complete & visible.
        cudaGridDependencySynchronize();

        float4* cp = (float4*)&g_cbar[4u * q];
        float4 c = *cp;
        *cp = make_float4(0.0f, 0.0f, 0.0f, 0.0f);

        float* o = out + 12u * (unsigned long long)q;
        o[2]  = v01.x - c.x;   // r0
        o[5]  = v01.z - c.y;   // r1
        o[8]  = v23.x - c.z;   // r2
        o[11] = v23.z - c.w;   // r3
    } else {
        cudaGridDependencySynchronize();
    }
}

extern "C" void kernel_launch(void* const* d_in, const int* in_sizes, int n_in,
                              void* d_out, int out_size) {
    // Inputs (JAX x64 disabled => "int64" arrays are int32 on device):
    // 0: vertex_attr (1M x 2) f32, 1: edgeij_pair (2 x 16M) i32 (row0 = src),
    // 2: edge_attr (16M x 2) f32, 3: g (unused), 4: batch (unused)
    const float* vertex_attr = (const float*)d_in[0];
    const int*   edge_src    = (const int*)d_in[1];
    const float* edge_attr   = (const float*)d_in[2];
    float*       out         = (float*)d_out;

    // Scatter: 16M edges / 8 = 2M threads = 128 x 15625 exact.
    {
        const int threads = 128;
        const int blocks  = (N_EDGES / 8) / threads;  // 15625
        scatter_kernel<<<blocks, threads>>>(edge_src, edge_attr);
    }

    // Finalize via PDL: allowed to launch as soon as scatter's blocks have
    // all fired the trigger; its pre-sync prefix overlaps scatter's tail.
    {
        cudaLaunchConfig_t cfg = {};
        cfg.gridDim  = dim3((N_VERTICES / 4 + 255) / 256);  // 977
        cfg.blockDim = dim3(256);
        cfg.stream   = 0;
        cudaLaunchAttribute attr[1];
        attr[0].id = cudaLaunchAttributeProgrammaticStreamSerialization;
        attr[0].val.programmaticStreamSerializationAllowed = 1;
        cfg.attrs    = attr;
        cfg.numAttrs = 1;
        cudaLaunchKernelEx(&cfg, finalize_kernel, vertex_attr, out);
    }
}

// round 11
// speedup vs baseline: 1.0560x; 1.0541x over previous
#include <cuda_runtime.h>

#define N_VERTICES 1000000
#define N_EDGES    16000000

// Scratch accumulator. Zero-initialized at module load; finalize_kernel
// resets it after consuming it, so every graph replay starts clean.
__device__ float g_cbar[N_VERTICES];

// Scatter: 8 edges per thread (2x int4 index loads + 4x float4 edge_attr
// loads + 8 spread-address fp32 REDs). Sits at the per-SM LSU spread-RED
// lane floor (~1.29 cyc/lane); keep minimal. 128 x 15625 = exactly 2M threads.
__global__ void __launch_bounds__(128, 16)
scatter_kernel(const int* __restrict__ src_idx,
               const float* __restrict__ edge_attr) {
    unsigned t = blockIdx.x * blockDim.x + threadIdx.x;   // [0, 2,000,000)
    const int4*   idx4 = (const int4*)src_idx;
    const float4* ea4  = (const float4*)edge_attr;

    int4   ia = idx4[2u * t];
    int4   ib = idx4[2u * t + 1u];
    float4 e0 = ea4[4u * t];
    float4 e1 = ea4[4u * t + 1u];
    float4 e2 = ea4[4u * t + 2u];
    float4 e3 = ea4[4u * t + 3u];

    atomicAdd(&g_cbar[ia.x], e0.y);
    atomicAdd(&g_cbar[ia.y], e0.w);
    atomicAdd(&g_cbar[ia.z], e1.y);
    atomicAdd(&g_cbar[ia.w], e1.w);
    atomicAdd(&g_cbar[ib.x], e2.y);
    atomicAdd(&g_cbar[ib.y], e2.w);
    atomicAdd(&g_cbar[ib.z], e3.y);
    atomicAdd(&g_cbar[ib.w], e3.w);
}

// Finalize: 8 vertices per thread (125K threads). 6 independent 16B loads
// (4x vertex_attr + 2x cbar) for MLP=6, then 6 aligned 16B row stores and
// 2 cbar resets. Latency-bound kernel -> ILP is the lever.
__global__ void __launch_bounds__(256, 8)
finalize_kernel(const float* __restrict__ vertex_attr,
                float* __restrict__ out) {
    unsigned q = blockIdx.x * blockDim.x + threadIdx.x;   // [0, 125K)
    if (q < N_VERTICES / 8) {
        const float4* va4 = (const float4*)vertex_attr;
        float4 v01 = va4[4u * q];        // (b0,x0,b1,x1)
        float4 v23 = va4[4u * q + 1u];   // (b2,x2,b3,x3)
        float4 v45 = va4[4u * q + 2u];   // (b4,x4,b5,x5)
        float4 v67 = va4[4u * q + 3u];   // (b6,x6,b7,x7)

        float4* cp0 = (float4*)&g_cbar[8u * q];
        float4* cp1 = (float4*)&g_cbar[8u * q + 4u];
        float4 c03 = *cp0;               // cbar 0..3
        float4 c47 = *cp1;               // cbar 4..7
        *cp0 = make_float4(0.0f, 0.0f, 0.0f, 0.0f);
        *cp1 = make_float4(0.0f, 0.0f, 0.0f, 0.0f);

        float4* o4 = (float4*)(out + 24u * (unsigned long long)q);
        o4[0] = make_float4(v01.x, v01.y, v01.x - c03.x, v01.z);      // b0,x0,r0,b1
        o4[1] = make_float4(v01.w, v01.z - c03.y, v23.x, v23.y);      // x1,r1,b2,x2
        o4[2] = make_float4(v23.x - c03.z, v23.z, v23.w, v23.z - c03.w); // r2,b3,x3,r3
        o4[3] = make_float4(v45.x, v45.y, v45.x - c47.x, v45.z);      // b4,x4,r4,b5
        o4[4] = make_float4(v45.w, v45.z - c47.y, v67.x, v67.y);      // x5,r5,b6,x6
        o4[5] = make_float4(v67.x - c47.z, v67.z, v67.w, v67.z - c47.w); // r6,b7,x7,r7
    }
}

extern "C" void kernel_launch(void* const* d_in, const int* in_sizes, int n_in,
                              void* d_out, int out_size) {
    // Inputs (JAX x64 disabled => "int64" arrays are int32 on device):
    // 0: vertex_attr (1M x 2) f32, 1: edgeij_pair (2 x 16M) i32 (row0 = src),
    // 2: edge_attr (16M x 2) f32, 3: g (unused), 4: batch (unused)
    const float* vertex_attr = (const float*)d_in[0];
    const int*   edge_src    = (const int*)d_in[1];
    const float* edge_attr   = (const float*)d_in[2];
    float*       out         = (float*)d_out;

    // Scatter: 16M edges / 8 = 2M threads = 128 x 15625 exact.
    {
        const int threads = 128;
        const int blocks  = (N_EDGES / 8) / threads;  // 15625
        scatter_kernel<<<blocks, threads>>>(edge_src, edge_attr);
    }
    // Finalize: 125K threads, 8 vertices each.
    {
        const int threads = 256;
        const int blocks  = (N_VERTICES / 8 + threads - 1) / threads;  // 489
        finalize_kernel<<<blocks, threads>>>(vertex_attr, out);
    }
}

// round 12
// speedup vs baseline: 1.0806x; 1.0233x over previous
#include <cuda_runtime.h>

#define N_VERTICES 1000000
#define N_EDGES    16000000
#define VPB        1024          // vertices per finalize block

// Scratch accumulator. Zero-initialized at module load; finalize_kernel
// resets it after consuming it, so every graph replay starts clean.
__device__ float g_cbar[N_VERTICES];

// Scatter: 8 edges per thread (2x int4 index loads + 4x float4 edge_attr
// loads + 8 spread-address fp32 REDs). Sits at the per-SM LSU spread-RED
// lane floor (~1.29 cyc/lane); keep minimal. 128 x 15625 = exactly 2M threads.
__global__ void __launch_bounds__(128, 16)
scatter_kernel(const int* __restrict__ src_idx,
               const float* __restrict__ edge_attr) {
    unsigned t = blockIdx.x * blockDim.x + threadIdx.x;   // [0, 2,000,000)
    const int4*   idx4 = (const int4*)src_idx;
    const float4* ea4  = (const float4*)edge_attr;

    int4   ia = idx4[2u * t];
    int4   ib = idx4[2u * t + 1u];
    float4 e0 = ea4[4u * t];
    float4 e1 = ea4[4u * t + 1u];
    float4 e2 = ea4[4u * t + 2u];
    float4 e3 = ea4[4u * t + 3u];

    atomicAdd(&g_cbar[ia.x], e0.y);
    atomicAdd(&g_cbar[ia.y], e0.w);
    atomicAdd(&g_cbar[ia.z], e1.y);
    atomicAdd(&g_cbar[ia.w], e1.w);
    atomicAdd(&g_cbar[ib.x], e2.y);
    atomicAdd(&g_cbar[ib.y], e2.w);
    atomicAdd(&g_cbar[ib.z], e3.y);
    atomicAdd(&g_cbar[ib.w], e3.w);
}

// Finalize: smem-staged for fully coalesced global traffic.
// Phase 1 (lane-strided): float2 va loads (256B/warp/instr), scalar cbar
// load+reset (128B/warp/instr), rows composed into smem (stride-3-word
// writes, conflict-free since gcd(3,32)=1).
// Phase 2: flush the 12KB row buffer as lane-contiguous float4 stores
// (every STG.128 = one 4-line coalesced wavefront).
// Tail block (576 vertices) still has float counts divisible by 4.
__global__ void __launch_bounds__(128, 8)
finalize_kernel(const float* __restrict__ vertex_attr,
                float* __restrict__ out) {
    __shared__ float srow[VPB * 3];          // 12 KB
    unsigned base = blockIdx.x * VPB;
    unsigned rem  = N_VERTICES - base;
    if (rem > VPB) rem = VPB;

#pragma unroll
    for (int k = 0; k < VPB / 128; k++) {
        unsigned l = threadIdx.x + 128u * k;     // local vertex
        if (l < rem) {
            unsigned v = base + l;
            float2 bx = ((const float2*)vertex_attr)[v];
            float  c  = g_cbar[v];
            g_cbar[v] = 0.0f;
            srow[3u * l + 0u] = bx.x;
            srow[3u * l + 1u] = bx.y;
            srow[3u * l + 2u] = bx.x - c;
        }
    }
    __syncthreads();

    const float4* s4 = (const float4*)srow;
    float4* o4 = (float4*)(out + 3ull * base);
    unsigned n4 = rem * 3u / 4u;                 // 768 (full) / 432 (tail)
#pragma unroll
    for (unsigned j = threadIdx.x; j < n4; j += 128u)
        o4[j] = s4[j];
}

extern "C" void kernel_launch(void* const* d_in, const int* in_sizes, int n_in,
                              void* d_out, int out_size) {
    // Inputs (JAX x64 disabled => "int64" arrays are int32 on device):
    // 0: vertex_attr (1M x 2) f32, 1: edgeij_pair (2 x 16M) i32 (row0 = src),
    // 2: edge_attr (16M x 2) f32, 3: g (unused), 4: batch (unused)
    const float* vertex_attr = (const float*)d_in[0];
    const int*   edge_src    = (const int*)d_in[1];
    const float* edge_attr   = (const float*)d_in[2];
    float*       out         = (float*)d_out;

    // Scatter: 16M edges / 8 = 2M threads = 128 x 15625 exact.
    {
        const int threads = 128;
        const int blocks  = (N_EDGES / 8) / threads;  // 15625
        scatter_kernel<<<blocks, threads>>>(edge_src, edge_attr);
    }
    // Finalize: 977 blocks x 128 threads, 1024 vertices per block.
    {
        const int blocks = (N_VERTICES + VPB - 1) / VPB;  // 977
        finalize_kernel<<<blocks, 128>>>(vertex_attr, out);
    }
}